// round 9
// baseline (speedup 1.0000x reference)
#include <cuda_runtime.h>
#include <cstdint>

#define B_  8
#define K_  19
#define C_  512
#define HW_ 16384

#define NSPLIT   8
#define S_CHUNK  2048                  // HW_/NSPLIT
#define TILE_S   256                   // probs tile (s) staged in smem
#define NT       (S_CHUNK / TILE_S)    // 8 tiles per chunk
#define NBUF     3                     // cp.async ring depth

// probs scratch: 8*19*16384 floats = 9.96 MB
__device__ float g_probs[B_ * K_ * HW_];
// partial results: [split][b][c][k] = 8 * 77824 floats = 2.49 MB
__device__ float g_part[NSPLIT * B_ * C_ * K_];

// packed fp32x2 FMA (sm_100+; PTX-only)
#define FMA2(acc, a, b) \
    asm("fma.rn.f32x2 %0, %1, %2, %0;" : "+l"(acc) : "l"(a), "l"(b))

__device__ __forceinline__ uint32_t smem_u32(const void* p) {
    uint32_t a;
    asm("{ .reg .u64 t; cvta.to.shared.u64 t, %1; cvt.u32.u64 %0, t; }" : "=r"(a) : "l"(p));
    return a;
}
__device__ __forceinline__ void cpasync16(uint32_t dst, const void* src) {
    asm volatile("cp.async.cg.shared.global [%0], [%1], 16;" :: "r"(dst), "l"(src));
}
#define CP_COMMIT()  asm volatile("cp.async.commit_group;" ::: "memory")
#define CP_WAIT(n)   asm volatile("cp.async.wait_group %0;" :: "n"(n) : "memory")

__device__ __forceinline__ float warpMax(float v) {
    #pragma unroll
    for (int o = 16; o; o >>= 1) v = fmaxf(v, __shfl_xor_sync(0xFFFFFFFFu, v, o));
    return v;
}
__device__ __forceinline__ float warpSum(float v) {
    #pragma unroll
    for (int o = 16; o; o >>= 1) v += __shfl_xor_sync(0xFFFFFFFFu, v, o);
    return v;
}

// ---------------------------------------------------------------------------
// Kernel 1: softmax over HW per (b,k) row. 152 CTAs x 512 threads.
// ---------------------------------------------------------------------------
__global__ __launch_bounds__(512) void softmax_kernel(const float* __restrict__ aux) {
    __shared__ float sh[16];
    const int row = blockIdx.x;
    const float4* x = reinterpret_cast<const float4*>(aux + (size_t)row * HW_);
    float4*       p = reinterpret_cast<float4*>(g_probs + (size_t)row * HW_);
    const int tid = threadIdx.x, lane = tid & 31, w = tid >> 5;

    float4 v[8];
    float m = -3.402823466e38f;
    #pragma unroll
    for (int i = 0; i < 8; i++) {
        v[i] = x[tid + i * 512];
        m = fmaxf(m, fmaxf(fmaxf(v[i].x, v[i].y), fmaxf(v[i].z, v[i].w)));
    }
    m = warpMax(m);
    if (lane == 0) sh[w] = m;
    __syncthreads();
    if (w == 0) {
        float t = (lane < 16) ? sh[lane] : -3.402823466e38f;
        t = warpMax(t);
        if (lane == 0) sh[0] = t;
    }
    __syncthreads();
    m = sh[0];
    __syncthreads();

    float s = 0.0f;
    #pragma unroll
    for (int i = 0; i < 8; i++) {
        v[i].x = __expf(v[i].x - m); v[i].y = __expf(v[i].y - m);
        v[i].z = __expf(v[i].z - m); v[i].w = __expf(v[i].w - m);
        s += (v[i].x + v[i].y) + (v[i].z + v[i].w);
    }
    s = warpSum(s);
    if (lane == 0) sh[w] = s;
    __syncthreads();
    if (w == 0) {
        float t = (lane < 16) ? sh[lane] : 0.0f;
        t = warpSum(t);
        if (lane == 0) sh[0] = t;
    }
    __syncthreads();
    const float inv = 1.0f / sh[0];
    #pragma unroll
    for (int i = 0; i < 8; i++) {
        v[i].x *= inv; v[i].y *= inv; v[i].z *= inv; v[i].w *= inv;
        p[tid + i * 512] = v[i];
    }
}

// ---------------------------------------------------------------------------
// Kernel 2: partial[b,c,k,split] = sum_{s in chunk} probs[b,k,s]*feats[b,c,s]
//
// grid = 8b * 4 c-blocks * 8 splits = 256 CTAs (one wave), 256 threads.
// CTA: (b, 128 c, 2048 s) = 8 tiles of 256 s.  Warp w: 16 c (c, c+64).
// Lane: c_sub = lane>>2, s_sub = lane&3 (16 s per step, f32x2 pairs).
// probs tile [19][256] in a 3-deep cp.async ring; feats prefetched one step
// ahead in regs; probs LDS software-pipelined DISTANCE-3 (issue LDS p[k+3]
// while FMAing p[k]) so the 29-cyc LDS latency is never the binding arm.
// ---------------------------------------------------------------------------
__global__ __launch_bounds__(256, 2) void gather_kernel(const float* __restrict__ feats) {
    __shared__ float sh[NBUF][K_ * TILE_S];            // 3 * 19456 B = 58368 B

    const int bid   = blockIdx.x;
    const int split = bid & (NSPLIT - 1);
    const int cb    = (bid >> 3) & 3;
    const int b     = bid >> 5;
    const int tid   = threadIdx.x;
    const int w     = tid >> 5, lane = tid & 31;
    const int c_sub = lane >> 2, s_sub = lane & 3;
    const int c     = cb * 128 + w * 8 + c_sub;        // second c: c + 64

    const size_t s_base = (size_t)split * S_CHUNK;
    const float* fbase = feats + ((size_t)b * C_ + c) * HW_ + s_base + s_sub * 4;
    const float* pbase = g_probs + (size_t)(b * K_) * HW_ + s_base;

    // tile loader: 19*256 floats = 1216 float4, 256 threads, 5 waves
    auto load_tile = [&](int t, int buf) {
        const float* src0 = pbase + t * TILE_S;
        uint32_t dst0 = smem_u32(&sh[buf][0]);
        #pragma unroll
        for (int i = 0; i < 5; i++) {
            int f = tid + i * 256;                     // float4 index
            if (f < (K_ * TILE_S) / 4) {
                int k = f >> 6;                        // 64 float4 per probs row
                int j = f & 63;
                cpasync16(dst0 + (uint32_t)f * 16, src0 + (size_t)k * HW_ + j * 4);
            }
        }
    };

    unsigned long long acc[K_][2];
    #pragma unroll
    for (int k = 0; k < K_; k++) { acc[k][0] = 0ull; acc[k][1] = 0ull; }

    // prologue: 2 tiles in flight
    load_tile(0, 0);
    CP_COMMIT();
    load_tile(1, 1);
    CP_COMMIT();

    // feats prefetch (step 0)
    ulonglong2 f0c = *reinterpret_cast<const ulonglong2*>(fbase);
    ulonglong2 f1c = *reinterpret_cast<const ulonglong2*>(fbase + 64 * HW_);

    for (int t = 0; t < NT; ++t) {
        __syncthreads();                   // readers of buf being overwritten are done
        if (t + 2 < NT) {
            load_tile(t + 2, (t + 2) % NBUF);
            CP_COMMIT();
            CP_WAIT(2);                    // tile t complete
        } else if (t + 1 < NT) {
            CP_WAIT(1);
        } else {
            CP_WAIT(0);
        }
        __syncthreads();                   // tile t visible to all warps

        const float* shb = sh[t % NBUF];

        #pragma unroll 2
        for (int i = 0; i < TILE_S / 16; ++i) {
            const int gi  = t * (TILE_S / 16) + i;
            const int gin = (gi + 1 < NT * (TILE_S / 16)) ? gi + 1 : gi;
            const ulonglong2 f0n = *reinterpret_cast<const ulonglong2*>(fbase + gin * 16);
            const ulonglong2 f1n = *reinterpret_cast<const ulonglong2*>(fbase + 64 * HW_ + gin * 16);
            const float* prow = shb + i * 16 + s_sub * 4;

            // distance-3 software pipeline on probs LDS
            ulonglong2 pw0 = *reinterpret_cast<const ulonglong2*>(prow);
            ulonglong2 pw1 = *reinterpret_cast<const ulonglong2*>(prow + TILE_S);
            ulonglong2 pw2 = *reinterpret_cast<const ulonglong2*>(prow + 2 * TILE_S);
            #pragma unroll
            for (int k = 0; k < K_; k++) {
                ulonglong2 pc;
                if ((k % 3) == 0) pc = pw0;
                else if ((k % 3) == 1) pc = pw1;
                else pc = pw2;
                if (k + 3 < K_) {
                    ulonglong2 pn =
                        *reinterpret_cast<const ulonglong2*>(prow + (k + 3) * TILE_S);
                    if ((k % 3) == 0) pw0 = pn;
                    else if ((k % 3) == 1) pw1 = pn;
                    else pw2 = pn;
                }
                FMA2(acc[k][0], pc.x, f0c.x);
                FMA2(acc[k][0], pc.y, f0c.y);
                FMA2(acc[k][1], pc.x, f1c.x);
                FMA2(acc[k][1], pc.y, f1c.y);
            }
            f0c = f0n;
            f1c = f1n;
        }
    }

    // reduce over s_sub (lanes xor 1,2), write partials (each exactly once)
    const size_t pout = (size_t)split * (B_ * C_ * K_) + ((size_t)b * C_ + c) * K_;
    #pragma unroll
    for (int k = 0; k < K_; k++) {
        #pragma unroll
        for (int cp = 0; cp < 2; cp++) {
            float2 v;
            asm("mov.b64 {%0, %1}, %2;" : "=f"(v.x), "=f"(v.y) : "l"(acc[k][cp]));
            float sum = v.x + v.y;
            sum += __shfl_xor_sync(0xFFFFFFFFu, sum, 1);
            sum += __shfl_xor_sync(0xFFFFFFFFu, sum, 2);
            if (s_sub == 0) g_part[pout + (size_t)cp * 64 * K_ + k] = sum;
        }
    }
}

// ---------------------------------------------------------------------------
// Kernel 3: out[i] = sum_split g_part[split][i]  (fixed order -> deterministic)
// ---------------------------------------------------------------------------
__global__ __launch_bounds__(256) void reduce_kernel(float* __restrict__ out) {
    const int i = blockIdx.x * 256 + threadIdx.x;
    if (i < B_ * C_ * K_) {
        float s = 0.0f;
        #pragma unroll
        for (int sp = 0; sp < NSPLIT; ++sp)
            s += g_part[(size_t)sp * (B_ * C_ * K_) + i];
        out[i] = s;
    }
}

extern "C" void kernel_launch(void* const* d_in, const int* in_sizes, int n_in,
                              void* d_out, int out_size) {
    const float* feats = (const float*)d_in[0];   // bb_feats [8,512,128,128]
    const float* aux   = (const float*)d_in[1];   // aux_out  [8,19,128,128]
    float* out = (float*)d_out;                   // [8,512,19,1] f32

    softmax_kernel<<<B_ * K_, 512>>>(aux);
    gather_kernel<<<B_ * 4 * NSPLIT, 256>>>(feats);
    reduce_kernel<<<(B_ * C_ * K_ + 255) / 256, 256>>>(out);
}

// round 13
// speedup vs baseline: 1.1797x; 1.1797x over previous
#include <cuda_runtime.h>
#include <cstdint>

#define B_  8
#define K_  19
#define C_  512
#define HW_ 16384

#define NSPLIT  8
#define S_PER   (HW_ / NSPLIT)        // 2048 s per CTA
#define TS      32                    // s per stage
#define NS      (S_PER / TS)          // 64 stages
#define NBUF    4

#define B_ROWS  24                    // 19 real k + 5 zero pad (3 n-tiles of 8)
#define A_ST    (128 * TS * 4)        // 16384 B per A stage
#define B_ST    (B_ROWS * TS * 4)     // 3072 B per B stage
#define DYN_BYTES (NBUF * (A_ST + B_ST) + 1024)

__device__ float g_probs[B_ * K_ * HW_];
__device__ float g_part[NSPLIT * B_ * C_ * K_];    // [sp][b][c][k]

#define SW128(off) ((uint32_t)(off) ^ ((((uint32_t)(off)) >> 3) & 0x70u))

__device__ __forceinline__ uint32_t smem_u32(const void* p) {
    uint32_t a;
    asm("{ .reg .u64 t; cvta.to.shared.u64 t, %1; cvt.u32.u64 %0, t; }" : "=r"(a) : "l"(p));
    return a;
}
__device__ __forceinline__ void cpasync16(uint32_t dst, const void* src) {
    asm volatile("cp.async.cg.shared.global [%0], [%1], 16;" :: "r"(dst), "l"(src));
}
#define CP_COMMIT()  asm volatile("cp.async.commit_group;" ::: "memory")
#define CP_WAIT(n)   asm volatile("cp.async.wait_group %0;" :: "n"(n) : "memory")

__device__ __forceinline__ float ldsf(uint32_t a) {
    float v;
    asm volatile("ld.shared.f32 %0, [%1];" : "=f"(v) : "r"(a));
    return v;
}
__device__ __forceinline__ uint32_t f2tf32(float x) {
    uint32_t r;
    asm("cvt.rna.tf32.f32 %0, %1;" : "=r"(r) : "f"(x));
    return r;
}
// D(16x8 f32) += A(16x8 tf32, row-major) * B(8x8 tf32, col-major)
#define MMA_TF32(D, A0, A1, A2, A3, Bb0, Bb1)                                  \
    asm volatile("mma.sync.aligned.m16n8k8.row.col.f32.tf32.tf32.f32 "         \
                 "{%0,%1,%2,%3}, {%4,%5,%6,%7}, {%8,%9}, {%0,%1,%2,%3};"       \
                 : "+f"((D)[0]), "+f"((D)[1]), "+f"((D)[2]), "+f"((D)[3])      \
                 : "r"(A0), "r"(A1), "r"(A2), "r"(A3), "r"(Bb0), "r"(Bb1))

__device__ __forceinline__ float warpMax(float v) {
    #pragma unroll
    for (int o = 16; o; o >>= 1) v = fmaxf(v, __shfl_xor_sync(0xFFFFFFFFu, v, o));
    return v;
}
__device__ __forceinline__ float warpSum(float v) {
    #pragma unroll
    for (int o = 16; o; o >>= 1) v += __shfl_xor_sync(0xFFFFFFFFu, v, o);
    return v;
}

// ---------------------------------------------------------------------------
// Kernel 1: softmax over HW per (b,k) row. 152 CTAs x 512 threads.
// ---------------------------------------------------------------------------
__global__ __launch_bounds__(512) void softmax_kernel(const float* __restrict__ aux) {
    __shared__ float sh[16];
    const int row = blockIdx.x;
    const float4* x = reinterpret_cast<const float4*>(aux + (size_t)row * HW_);
    float4*       p = reinterpret_cast<float4*>(g_probs + (size_t)row * HW_);
    const int tid = threadIdx.x, lane = tid & 31, w = tid >> 5;

    float4 v[8];
    float m = -3.402823466e38f;
    #pragma unroll
    for (int i = 0; i < 8; i++) {
        v[i] = x[tid + i * 512];
        m = fmaxf(m, fmaxf(fmaxf(v[i].x, v[i].y), fmaxf(v[i].z, v[i].w)));
    }
    m = warpMax(m);
    if (lane == 0) sh[w] = m;
    __syncthreads();
    if (w == 0) {
        float t = (lane < 16) ? sh[lane] : -3.402823466e38f;
        t = warpMax(t);
        if (lane == 0) sh[0] = t;
    }
    __syncthreads();
    m = sh[0];
    __syncthreads();

    float s = 0.0f;
    #pragma unroll
    for (int i = 0; i < 8; i++) {
        v[i].x = __expf(v[i].x - m); v[i].y = __expf(v[i].y - m);
        v[i].z = __expf(v[i].z - m); v[i].w = __expf(v[i].w - m);
        s += (v[i].x + v[i].y) + (v[i].z + v[i].w);
    }
    s = warpSum(s);
    if (lane == 0) sh[w] = s;
    __syncthreads();
    if (w == 0) {
        float t = (lane < 16) ? sh[lane] : 0.0f;
        t = warpSum(t);
        if (lane == 0) sh[0] = t;
    }
    __syncthreads();
    const float inv = 1.0f / sh[0];
    #pragma unroll
    for (int i = 0; i < 8; i++) {
        v[i].x *= inv; v[i].y *= inv; v[i].z *= inv; v[i].w *= inv;
        p[tid + i * 512] = v[i];
    }
}

// ---------------------------------------------------------------------------
// Kernel 2: split-tf32 mma.sync GEMM.
//   D[c,k] = sum_s feats[c,s] * probs[k,s]    (per b; s split across CTAs)
//
// grid = 8b * 4 c-tiles * 8 s-splits = 256 CTAs, 256 threads (8 warps).
// Stage = 32 s: A [128 c][32 s] f32 SW128 (16 KB), B [24 k][32 s] (3 KB,
// rows 19..23 zeroed once).  4-stage cp.async ring (3 in flight).
// Reader addressing uses the analytic swizzle decomposition
//   addr(row, col) = row*128 + q*4 + (col16 ^ ((row&7)*16))
// which matches the writers' full-offset SW128 exactly (the R12 bug was
// SW128(rowbase)+coloff != SW128(rowbase+coloff)).
// Precision: a = a_hi+a_lo, b = b_hi+b_lo; 3 MMAs (ah*bh, al*bh, ah*bl)
// -> residual ~ a_lo*b_lo ~ 2^-22, rel_err ~1e-6.
// ---------------------------------------------------------------------------
__global__ __launch_bounds__(256, 2) void gather_mma(const float* __restrict__ feats) {
    extern __shared__ char dsm_raw[];
    uint32_t base = smem_u32(dsm_raw);
    base = (base + 1023u) & ~1023u;
    const uint32_t aBase = base;
    const uint32_t bBase = base + NBUF * A_ST;
    char* dsm = dsm_raw + (base - smem_u32(dsm_raw));

    const int tid = threadIdx.x;
    const int w = tid >> 5, lane = tid & 31;
    const int sp = blockIdx.x & 7;
    const int ct = (blockIdx.x >> 3) & 3;
    const int b  = blockIdx.x >> 5;

    // zero B pad rows (19..23) in all buffers; cp.async never touches them
    for (int i = tid; i < NBUF * 5 * TS; i += 256) {
        const int buf = i / (5 * TS);
        const int rem = i - buf * (5 * TS);
        const int r   = 19 + rem / TS;
        const int col = rem - (r - 19) * TS;
        *reinterpret_cast<float*>(dsm + NBUF * A_ST + buf * B_ST +
                                  SW128(r * 128 + col * 4)) = 0.0f;
    }
    __syncthreads();

    // ---- cp.async assignments ----
    const float* aSrc[4];
    uint32_t     aDst[4];
    #pragma unroll
    for (int j = 0; j < 4; j++) {
        const int g   = tid + j * 256;                 // 16B granule, 0..1023
        const int row = g >> 3;                        // c row 0..127
        const int col = g & 7;                         // 16B col
        aSrc[j] = feats + ((size_t)(b * C_) + ct * 128 + row) * HW_
                        + sp * S_PER + col * 4;
        aDst[j] = SW128(g * 16);
    }
    const bool   bAct = (tid < K_ * 8);                // 152 granules
    const float* bSrc;
    uint32_t     bDst;
    {
        const int g   = bAct ? tid : 0;
        const int k   = g >> 3;
        const int col = g & 7;
        bSrc = g_probs + ((size_t)(b * K_) + k) * HW_ + sp * S_PER + col * 4;
        bDst = SW128(g * 16);
    }

    auto issue = [&](int t) {
        const uint32_t aS = aBase + (t & 3) * A_ST;
        const uint32_t bS = bBase + (t & 3) * B_ST;
        const int off = t * TS;
        #pragma unroll
        for (int j = 0; j < 4; j++) cpasync16(aS + aDst[j], aSrc[j] + off);
        if (bAct) cpasync16(bS + bDst, bSrc + off);
    };

    // ---- fragment read addressing (analytic swizzle decomposition) ----
    const int rA = lane >> 2;                          // 0..7
    const int q  = lane & 3;
    const uint32_t mask = (uint32_t)rA * 16u;          // XOR mask, bits 4-6
    const uint32_t baseA0 = (uint32_t)(w * 16 + rA) * 128u + q * 4u;
    const uint32_t baseA1 = baseA0 + 8u * 128u;
    uint32_t baseB[3];
    #pragma unroll
    for (int nt = 0; nt < 3; nt++)
        baseB[nt] = (uint32_t)(nt * 8 + rA) * 128u + q * 4u;

    float d[3][4];
    #pragma unroll
    for (int nt = 0; nt < 3; nt++)
        #pragma unroll
        for (int j = 0; j < 4; j++) d[nt][j] = 0.0f;

    // prologue: 3 stages in flight
    issue(0); CP_COMMIT();
    issue(1); CP_COMMIT();
    issue(2); CP_COMMIT();

    for (int t = 0; t < NS; ++t) {
        __syncthreads();                               // done reading recycled buffer
        if (t + 3 < NS) { issue(t + 3); CP_COMMIT(); CP_WAIT(3); }
        else if (t + 2 < NS) { CP_WAIT(2); }
        else if (t + 1 < NS) { CP_WAIT(1); }
        else                 { CP_WAIT(0); }
        __syncthreads();                               // stage t visible

        const uint32_t aS = aBase + (t & 3) * A_ST;
        const uint32_t bS = bBase + (t & 3) * B_ST;

        #pragma unroll
        for (int ch = 0; ch < 4; ++ch) {               // 8-s chunks
            const uint32_t c0 = (uint32_t)(ch * 32) ^ mask;        // col s0..s0+3
            const uint32_t c1 = (uint32_t)(ch * 32 + 16) ^ mask;   // col s0+4..s0+7
            const float a0 = ldsf(aS + baseA0 + c0);
            const float a1 = ldsf(aS + baseA1 + c0);
            const float a2 = ldsf(aS + baseA0 + c1);
            const float a3 = ldsf(aS + baseA1 + c1);
            const uint32_t ah0 = f2tf32(a0), ah1 = f2tf32(a1);
            const uint32_t ah2 = f2tf32(a2), ah3 = f2tf32(a3);
            const uint32_t al0 = f2tf32(a0 - __uint_as_float(ah0));
            const uint32_t al1 = f2tf32(a1 - __uint_as_float(ah1));
            const uint32_t al2 = f2tf32(a2 - __uint_as_float(ah2));
            const uint32_t al3 = f2tf32(a3 - __uint_as_float(ah3));
            #pragma unroll
            for (int nt = 0; nt < 3; ++nt) {
                const float b0f = ldsf(bS + baseB[nt] + c0);
                const float b1f = ldsf(bS + baseB[nt] + c1);
                const uint32_t bh0 = f2tf32(b0f), bh1 = f2tf32(b1f);
                const uint32_t bl0 = f2tf32(b0f - __uint_as_float(bh0));
                const uint32_t bl1 = f2tf32(b1f - __uint_as_float(bh1));
                MMA_TF32(d[nt], ah0, ah1, ah2, ah3, bh0, bh1);
                MMA_TF32(d[nt], al0, al1, al2, al3, bh0, bh1);
                MMA_TF32(d[nt], ah0, ah1, ah2, ah3, bl0, bl1);
            }
        }
    }

    // ---- epilogue: write split partials (each element exactly once) ----
    const int crow = ct * 128 + w * 16 + rA;
    const size_t o0 = ((size_t)(sp * B_ + b) * C_ + crow) * K_;
    const size_t o1 = ((size_t)(sp * B_ + b) * C_ + crow + 8) * K_;
    #pragma unroll
    for (int nt = 0; nt < 3; ++nt) {
        const int k0 = nt * 8 + 2 * q;
        if (k0 < K_) {
            g_part[o0 + k0] = d[nt][0];
            g_part[o1 + k0] = d[nt][2];
        }
        if (k0 + 1 < K_) {
            g_part[o0 + k0 + 1] = d[nt][1];
            g_part[o1 + k0 + 1] = d[nt][3];
        }
    }
}

// ---------------------------------------------------------------------------
// Kernel 3: out[i] = sum_split g_part[split][i]  (fixed order -> deterministic)
// ---------------------------------------------------------------------------
__global__ __launch_bounds__(256) void reduce_kernel(float* __restrict__ out) {
    const int i = blockIdx.x * 256 + threadIdx.x;
    if (i < B_ * C_ * K_) {
        float s = 0.0f;
        #pragma unroll
        for (int sp = 0; sp < NSPLIT; ++sp)
            s += g_part[(size_t)sp * (B_ * C_ * K_) + i];
        out[i] = s;
    }
}

extern "C" void kernel_launch(void* const* d_in, const int* in_sizes, int n_in,
                              void* d_out, int out_size) {
    const float* feats = (const float*)d_in[0];   // bb_feats [8,512,128,128]
    const float* aux   = (const float*)d_in[1];   // aux_out  [8,19,128,128]
    float* out = (float*)d_out;                   // [8,512,19,1] f32

    cudaFuncSetAttribute(gather_mma, cudaFuncAttributeMaxDynamicSharedMemorySize,
                         DYN_BYTES);

    softmax_kernel<<<B_ * K_, 512>>>(aux);
    gather_mma<<<B_ * 4 * NSPLIT, 256, DYN_BYTES>>>(feats);
    reduce_kernel<<<(B_ * C_ * K_ + 255) / 256, 256>>>(out);
}

// round 14
// speedup vs baseline: 1.6325x; 1.3838x over previous
#include <cuda_runtime.h>
#include <cstdint>

#define B_  8
#define K_  19
#define C_  512
#define HW_ 16384

#define NSPLIT  16
#define S_PER   (HW_ / NSPLIT)        // 1024 s per CTA
#define TS      32                    // s per stage
#define NS      (S_PER / TS)          // 32 stages
#define NBUF    3

#define B_ROWS  24                    // 19 real k + 5 zero pad (3 n-tiles of 8)
#define A_ST    (128 * TS * 4)        // 16384 B per A stage
#define B_ST    (B_ROWS * TS * 4)     // 3072 B per B stage
#define DYN_BYTES (NBUF * (A_ST + B_ST) + 1024)

__device__ float g_probs[B_ * K_ * HW_];           // tf32-rounded values
__device__ float g_part[NSPLIT * B_ * C_ * K_];    // [sp][b][c][k]

#define SW128(off) ((uint32_t)(off) ^ ((((uint32_t)(off)) >> 3) & 0x70u))

__device__ __forceinline__ uint32_t smem_u32(const void* p) {
    uint32_t a;
    asm("{ .reg .u64 t; cvta.to.shared.u64 t, %1; cvt.u32.u64 %0, t; }" : "=r"(a) : "l"(p));
    return a;
}
__device__ __forceinline__ void cpasync16(uint32_t dst, const void* src) {
    asm volatile("cp.async.cg.shared.global [%0], [%1], 16;" :: "r"(dst), "l"(src));
}
#define CP_COMMIT()  asm volatile("cp.async.commit_group;" ::: "memory")
#define CP_WAIT(n)   asm volatile("cp.async.wait_group %0;" :: "n"(n) : "memory")

__device__ __forceinline__ float ldsf(uint32_t a) {
    float v;
    asm volatile("ld.shared.f32 %0, [%1];" : "=f"(v) : "r"(a));
    return v;
}
__device__ __forceinline__ uint32_t ldsu(uint32_t a) {
    uint32_t v;
    asm volatile("ld.shared.b32 %0, [%1];" : "=r"(v) : "r"(a));
    return v;
}
__device__ __forceinline__ uint32_t f2tf32(float x) {
    uint32_t r;
    asm("cvt.rna.tf32.f32 %0, %1;" : "=r"(r) : "f"(x));
    return r;
}
// D(16x8 f32) += A(16x8 tf32, row-major) * B(8x8 tf32, col-major)
#define MMA_TF32(D, A0, A1, A2, A3, Bb0, Bb1)                                  \
    asm volatile("mma.sync.aligned.m16n8k8.row.col.f32.tf32.tf32.f32 "         \
                 "{%0,%1,%2,%3}, {%4,%5,%6,%7}, {%8,%9}, {%0,%1,%2,%3};"       \
                 : "+f"((D)[0]), "+f"((D)[1]), "+f"((D)[2]), "+f"((D)[3])      \
                 : "r"(A0), "r"(A1), "r"(A2), "r"(A3), "r"(Bb0), "r"(Bb1))

__device__ __forceinline__ float warpMax(float v) {
    #pragma unroll
    for (int o = 16; o; o >>= 1) v = fmaxf(v, __shfl_xor_sync(0xFFFFFFFFu, v, o));
    return v;
}
__device__ __forceinline__ float warpSum(float v) {
    #pragma unroll
    for (int o = 16; o; o >>= 1) v += __shfl_xor_sync(0xFFFFFFFFu, v, o);
    return v;
}

// ---------------------------------------------------------------------------
// Kernel 1: softmax over HW per (b,k) row; output rounded to tf32 values.
// ---------------------------------------------------------------------------
__global__ __launch_bounds__(512) void softmax_kernel(const float* __restrict__ aux) {
    __shared__ float sh[16];
    const int row = blockIdx.x;
    const float4* x = reinterpret_cast<const float4*>(aux + (size_t)row * HW_);
    float4*       p = reinterpret_cast<float4*>(g_probs + (size_t)row * HW_);
    const int tid = threadIdx.x, lane = tid & 31, w = tid >> 5;

    float4 v[8];
    float m = -3.402823466e38f;
    #pragma unroll
    for (int i = 0; i < 8; i++) {
        v[i] = x[tid + i * 512];
        m = fmaxf(m, fmaxf(fmaxf(v[i].x, v[i].y), fmaxf(v[i].z, v[i].w)));
    }
    m = warpMax(m);
    if (lane == 0) sh[w] = m;
    __syncthreads();
    if (w == 0) {
        float t = (lane < 16) ? sh[lane] : -3.402823466e38f;
        t = warpMax(t);
        if (lane == 0) sh[0] = t;
    }
    __syncthreads();
    m = sh[0];
    __syncthreads();

    float s = 0.0f;
    #pragma unroll
    for (int i = 0; i < 8; i++) {
        v[i].x = __expf(v[i].x - m); v[i].y = __expf(v[i].y - m);
        v[i].z = __expf(v[i].z - m); v[i].w = __expf(v[i].w - m);
        s += (v[i].x + v[i].y) + (v[i].z + v[i].w);
    }
    s = warpSum(s);
    if (lane == 0) sh[w] = s;
    __syncthreads();
    if (w == 0) {
        float t = (lane < 16) ? sh[lane] : 0.0f;
        t = warpSum(t);
        if (lane == 0) sh[0] = t;
    }
    __syncthreads();
    const float inv = 1.0f / sh[0];
    #pragma unroll
    for (int i = 0; i < 8; i++) {
        v[i].x = __uint_as_float(f2tf32(v[i].x * inv));
        v[i].y = __uint_as_float(f2tf32(v[i].y * inv));
        v[i].z = __uint_as_float(f2tf32(v[i].z * inv));
        v[i].w = __uint_as_float(f2tf32(v[i].w * inv));
        p[tid + i * 512] = v[i];
    }
}

// ---------------------------------------------------------------------------
// Kernel 2: tf32 mma.sync GEMM.
//   D[c,k] = sum_s feats[c,s] * probs[k,s]    (per b; s split across CTAs)
//
// grid = 8b * 4 c-tiles * 16 s-splits = 512 CTAs, 256 threads, 3 CTAs/SM.
// Stage = 32 s: A [128 c][32 s] f32 SW128 (16 KB), B [24 k][32 s] tf32
// (3 KB, pad rows zeroed once).  3-stage cp.async ring.
// B is PRE-ROUNDED to tf32 by the softmax kernel -> loaded as raw bits,
// no per-warp conversion.  A: one cvt per fragment reg.  Single MMA per
// n-tile (tf32 eps ~1.2e-4 rel err, 8x under the 1e-3 threshold).
// Reader swizzle = analytic decomposition matching writers exactly.
// ---------------------------------------------------------------------------
__global__ __launch_bounds__(256, 3) void gather_mma(const float* __restrict__ feats) {
    extern __shared__ char dsm_raw[];
    uint32_t base = smem_u32(dsm_raw);
    base = (base + 1023u) & ~1023u;
    const uint32_t aBase = base;
    const uint32_t bBase = base + NBUF * A_ST;
    char* dsm = dsm_raw + (base - smem_u32(dsm_raw));

    const int tid = threadIdx.x;
    const int w = tid >> 5, lane = tid & 31;
    const int sp = blockIdx.x & (NSPLIT - 1);
    const int ct = (blockIdx.x >> 4) & 3;
    const int b  = blockIdx.x >> 6;

    // zero B pad rows (19..23) in all buffers; cp.async never touches them
    for (int i = tid; i < NBUF * 5 * TS; i += 256) {
        const int buf = i / (5 * TS);
        const int rem = i - buf * (5 * TS);
        const int r   = 19 + rem / TS;
        const int col = rem - (r - 19) * TS;
        *reinterpret_cast<float*>(dsm + NBUF * A_ST + buf * B_ST +
                                  SW128(r * 128 + col * 4)) = 0.0f;
    }
    __syncthreads();

    // ---- cp.async assignments ----
    const float* aSrc[4];
    uint32_t     aDst[4];
    #pragma unroll
    for (int j = 0; j < 4; j++) {
        const int g   = tid + j * 256;                 // 16B granule, 0..1023
        const int row = g >> 3;                        // c row 0..127
        const int col = g & 7;                         // 16B col
        aSrc[j] = feats + ((size_t)(b * C_) + ct * 128 + row) * HW_
                        + sp * S_PER + col * 4;
        aDst[j] = SW128(g * 16);
    }
    const bool   bAct = (tid < K_ * 8);                // 152 granules
    const float* bSrc;
    uint32_t     bDst;
    {
        const int g   = bAct ? tid : 0;
        const int k   = g >> 3;
        const int col = g & 7;
        bSrc = g_probs + ((size_t)(b * K_) + k) * HW_ + sp * S_PER + col * 4;
        bDst = SW128(g * 16);
    }

    auto issue = [&](int t) {
        const uint32_t aS = aBase + (t % NBUF) * A_ST;
        const uint32_t bS = bBase + (t % NBUF) * B_ST;
        const int off = t * TS;
        #pragma unroll
        for (int j = 0; j < 4; j++) cpasync16(aS + aDst[j], aSrc[j] + off);
        if (bAct) cpasync16(bS + bDst, bSrc + off);
    };

    // ---- fragment read addressing (analytic swizzle decomposition) ----
    const int rA = lane >> 2;                          // 0..7
    const int q  = lane & 3;
    const uint32_t mask = (uint32_t)rA * 16u;          // XOR mask, bits 4-6
    const uint32_t baseA0 = (uint32_t)(w * 16 + rA) * 128u + q * 4u;
    const uint32_t baseA1 = baseA0 + 8u * 128u;
    uint32_t baseB[3];
    #pragma unroll
    for (int nt = 0; nt < 3; nt++)
        baseB[nt] = (uint32_t)(nt * 8 + rA) * 128u + q * 4u;

    float d[3][4];
    #pragma unroll
    for (int nt = 0; nt < 3; nt++)
        #pragma unroll
        for (int j = 0; j < 4; j++) d[nt][j] = 0.0f;

    // prologue: 2 stages in flight
    issue(0); CP_COMMIT();
    issue(1); CP_COMMIT();

    for (int t = 0; t < NS; ++t) {
        __syncthreads();                               // done reading recycled buffer
        if (t + 2 < NS) { issue(t + 2); CP_COMMIT(); CP_WAIT(2); }
        else if (t + 1 < NS) { CP_WAIT(1); }
        else                 { CP_WAIT(0); }
        __syncthreads();                               // stage t visible

        const uint32_t aS = aBase + (t % NBUF) * A_ST;
        const uint32_t bS = bBase + (t % NBUF) * B_ST;

        #pragma unroll
        for (int ch = 0; ch < 4; ++ch) {               // 8-s chunks
            const uint32_t c0 = (uint32_t)(ch * 32) ^ mask;        // s0..s0+3
            const uint32_t c1 = (uint32_t)(ch * 32 + 16) ^ mask;   // s0+4..s0+7
            const uint32_t ah0 = f2tf32(ldsf(aS + baseA0 + c0));
            const uint32_t ah1 = f2tf32(ldsf(aS + baseA1 + c0));
            const uint32_t ah2 = f2tf32(ldsf(aS + baseA0 + c1));
            const uint32_t ah3 = f2tf32(ldsf(aS + baseA1 + c1));
            #pragma unroll
            for (int nt = 0; nt < 3; ++nt) {
                const uint32_t b0 = ldsu(bS + baseB[nt] + c0);     // already tf32
                const uint32_t b1 = ldsu(bS + baseB[nt] + c1);
                MMA_TF32(d[nt], ah0, ah1, ah2, ah3, b0, b1);
            }
        }
    }

    // ---- epilogue: write split partials (each element exactly once) ----
    const int crow = ct * 128 + w * 16 + rA;
    const size_t o0 = ((size_t)(sp * B_ + b) * C_ + crow) * K_;
    const size_t o1 = ((size_t)(sp * B_ + b) * C_ + crow + 8) * K_;
    #pragma unroll
    for (int nt = 0; nt < 3; ++nt) {
        const int k0 = nt * 8 + 2 * q;
        if (k0 < K_) {
            g_part[o0 + k0] = d[nt][0];
            g_part[o1 + k0] = d[nt][2];
        }
        if (k0 + 1 < K_) {
            g_part[o0 + k0 + 1] = d[nt][1];
            g_part[o1 + k0 + 1] = d[nt][3];
        }
    }
}

// ---------------------------------------------------------------------------
// Kernel 3: out[i] = sum_split g_part[split][i]  (fixed order -> deterministic)
// ---------------------------------------------------------------------------
__global__ __launch_bounds__(256) void reduce_kernel(float* __restrict__ out) {
    const int i = blockIdx.x * 256 + threadIdx.x;
    if (i < B_ * C_ * K_) {
        float s = 0.0f;
        #pragma unroll
        for (int sp = 0; sp < NSPLIT; ++sp)
            s += g_part[(size_t)sp * (B_ * C_ * K_) + i];
        out[i] = s;
    }
}

extern "C" void kernel_launch(void* const* d_in, const int* in_sizes, int n_in,
                              void* d_out, int out_size) {
    const float* feats = (const float*)d_in[0];   // bb_feats [8,512,128,128]
    const float* aux   = (const float*)d_in[1];   // aux_out  [8,19,128,128]
    float* out = (float*)d_out;                   // [8,512,19,1] f32

    cudaFuncSetAttribute(gather_mma, cudaFuncAttributeMaxDynamicSharedMemorySize,
                         DYN_BYTES);

    softmax_kernel<<<B_ * K_, 512>>>(aux);
    gather_mma<<<B_ * 4 * NSPLIT, 256, DYN_BYTES>>>(feats);
    reduce_kernel<<<(B_ * C_ * K_ + 255) / 256, 256>>>(out);
}

// round 15
// speedup vs baseline: 1.8110x; 1.1093x over previous
#include <cuda_runtime.h>
#include <cstdint>

#define B_  8
#define K_  19
#define C_  512
#define HW_ 16384

#define NSPLIT  13                    // grid 8*4*13 = 416 <= 444 slots: ONE wave
#define TS      32                    // s per stage
#define NST_TOT (HW_ / TS)            // 512 stages total; first 5 splits get 40
#define NBUF    3

#define B_ROWS  24                    // 19 real k + 5 zero pad (3 n-tiles of 8)
#define A_ST    (128 * TS * 4)        // 16384 B per A stage
#define B_ST    (B_ROWS * TS * 4)     // 3072 B per B stage
#define DYN_BYTES (NBUF * (A_ST + B_ST) + 1024)

__device__ float g_probs[B_ * K_ * HW_];           // tf32-rounded values
__device__ float g_part[NSPLIT * B_ * C_ * K_];    // [sp][b][c][k]

#define SW128(off) ((uint32_t)(off) ^ ((((uint32_t)(off)) >> 3) & 0x70u))

__device__ __forceinline__ uint32_t smem_u32(const void* p) {
    uint32_t a;
    asm("{ .reg .u64 t; cvta.to.shared.u64 t, %1; cvt.u32.u64 %0, t; }" : "=r"(a) : "l"(p));
    return a;
}
__device__ __forceinline__ void cpasync16(uint32_t dst, const void* src) {
    asm volatile("cp.async.cg.shared.global [%0], [%1], 16;" :: "r"(dst), "l"(src));
}
#define CP_COMMIT()  asm volatile("cp.async.commit_group;" ::: "memory")
#define CP_WAIT(n)   asm volatile("cp.async.wait_group %0;" :: "n"(n) : "memory")

__device__ __forceinline__ float ldsf(uint32_t a) {
    float v;
    asm volatile("ld.shared.f32 %0, [%1];" : "=f"(v) : "r"(a));
    return v;
}
__device__ __forceinline__ uint32_t ldsu(uint32_t a) {
    uint32_t v;
    asm volatile("ld.shared.b32 %0, [%1];" : "=r"(v) : "r"(a));
    return v;
}
__device__ __forceinline__ uint32_t f2tf32(float x) {
    uint32_t r;
    asm("cvt.rna.tf32.f32 %0, %1;" : "=r"(r) : "f"(x));
    return r;
}
// D(16x8 f32) += A(16x8 tf32, row-major) * B(8x8 tf32, col-major)
#define MMA_TF32(D, A0, A1, A2, A3, Bb0, Bb1)                                  \
    asm volatile("mma.sync.aligned.m16n8k8.row.col.f32.tf32.tf32.f32 "         \
                 "{%0,%1,%2,%3}, {%4,%5,%6,%7}, {%8,%9}, {%0,%1,%2,%3};"       \
                 : "+f"((D)[0]), "+f"((D)[1]), "+f"((D)[2]), "+f"((D)[3])      \
                 : "r"(A0), "r"(A1), "r"(A2), "r"(A3), "r"(Bb0), "r"(Bb1))

__device__ __forceinline__ float warpMax(float v) {
    #pragma unroll
    for (int o = 16; o; o >>= 1) v = fmaxf(v, __shfl_xor_sync(0xFFFFFFFFu, v, o));
    return v;
}
__device__ __forceinline__ float warpSum(float v) {
    #pragma unroll
    for (int o = 16; o; o >>= 1) v += __shfl_xor_sync(0xFFFFFFFFu, v, o);
    return v;
}

// ---------------------------------------------------------------------------
// Kernel 1: softmax over HW per (b,k) row; output rounded to tf32 values.
// 152 CTAs x 256 threads, 2 CTAs/SM -> one wave (no straggler serialization).
// Each thread holds 64 elements (16 float4) in registers.
// ---------------------------------------------------------------------------
__global__ __launch_bounds__(256, 2) void softmax_kernel(const float* __restrict__ aux) {
    __shared__ float sh[8];
    const int row = blockIdx.x;
    const float4* x = reinterpret_cast<const float4*>(aux + (size_t)row * HW_);
    float4*       p = reinterpret_cast<float4*>(g_probs + (size_t)row * HW_);
    const int tid = threadIdx.x, lane = tid & 31, w = tid >> 5;

    float4 v[16];
    float m = -3.402823466e38f;
    #pragma unroll
    for (int i = 0; i < 16; i++) {
        v[i] = x[tid + i * 256];
        m = fmaxf(m, fmaxf(fmaxf(v[i].x, v[i].y), fmaxf(v[i].z, v[i].w)));
    }
    m = warpMax(m);
    if (lane == 0) sh[w] = m;
    __syncthreads();
    if (w == 0) {
        float t = (lane < 8) ? sh[lane] : -3.402823466e38f;
        t = warpMax(t);
        if (lane == 0) sh[0] = t;
    }
    __syncthreads();
    m = sh[0];
    __syncthreads();

    float s = 0.0f;
    #pragma unroll
    for (int i = 0; i < 16; i++) {
        v[i].x = __expf(v[i].x - m); v[i].y = __expf(v[i].y - m);
        v[i].z = __expf(v[i].z - m); v[i].w = __expf(v[i].w - m);
        s += (v[i].x + v[i].y) + (v[i].z + v[i].w);
    }
    s = warpSum(s);
    if (lane == 0) sh[w] = s;
    __syncthreads();
    if (w == 0) {
        float t = (lane < 8) ? sh[lane] : 0.0f;
        t = warpSum(t);
        if (lane == 0) sh[0] = t;
    }
    __syncthreads();
    const float inv = 1.0f / sh[0];
    #pragma unroll
    for (int i = 0; i < 16; i++) {
        v[i].x = __uint_as_float(f2tf32(v[i].x * inv));
        v[i].y = __uint_as_float(f2tf32(v[i].y * inv));
        v[i].z = __uint_as_float(f2tf32(v[i].z * inv));
        v[i].w = __uint_as_float(f2tf32(v[i].w * inv));
        p[tid + i * 256] = v[i];
    }
}

// ---------------------------------------------------------------------------
// Kernel 2: tf32 mma.sync GEMM.
//   D[c,k] = sum_s feats[c,s] * probs[k,s]    (per b; s split across CTAs)
//
// grid = 8b * 4 c-tiles * 13 s-splits = 416 CTAs, 256 threads, 3 CTAs/SM
// -> SINGLE wave (416 <= 444).  512 total 32-s stages split unevenly:
// splits 0..4 get 40 stages, splits 5..12 get 39 (5*40 + 8*39 = 512).
// Stage: A [128 c][32 s] f32 SW128 (16 KB), B [24 k][32 s] tf32 (3 KB).
// 3-stage cp.async ring.  B pre-rounded to tf32 by softmax (raw-bit loads).
// Reader swizzle = analytic decomposition matching writers exactly.
// ---------------------------------------------------------------------------
__global__ __launch_bounds__(256, 3) void gather_mma(const float* __restrict__ feats) {
    extern __shared__ char dsm_raw[];
    uint32_t base = smem_u32(dsm_raw);
    base = (base + 1023u) & ~1023u;
    const uint32_t aBase = base;
    const uint32_t bBase = base + NBUF * A_ST;
    char* dsm = dsm_raw + (base - smem_u32(dsm_raw));

    const int tid = threadIdx.x;
    const int w = tid >> 5, lane = tid & 31;
    const int sp = blockIdx.x % NSPLIT;
    const int r2 = blockIdx.x / NSPLIT;
    const int ct = r2 & 3;
    const int b  = r2 >> 2;

    // per-split stage range (uneven): first 5 splits have 40 stages, rest 39
    const int NSl   = 39 + (sp < 5 ? 1 : 0);
    const int s_off = (sp * 39 + (sp < 5 ? sp : 5)) * TS;

    // zero B pad rows (19..23) in all buffers; cp.async never touches them
    for (int i = tid; i < NBUF * 5 * TS; i += 256) {
        const int buf = i / (5 * TS);
        const int rem = i - buf * (5 * TS);
        const int r   = 19 + rem / TS;
        const int col = rem - (r - 19) * TS;
        *reinterpret_cast<float*>(dsm + NBUF * A_ST + buf * B_ST +
                                  SW128(r * 128 + col * 4)) = 0.0f;
    }
    __syncthreads();

    // ---- cp.async assignments ----
    // granule g = tid + j*256: row=g>>3, col=g&7.  aSrc[j]=aSrc0+j*32*HW_,
    // aDst[j]=aDst0+j*4096 (swizzle bits depend only on tid, proven).
    const float* aSrc0 = feats + ((size_t)(b * C_) + ct * 128 + (tid >> 3)) * HW_
                         + s_off + (tid & 7) * 4;
    const uint32_t aDst0 = SW128((uint32_t)tid * 16u);
    const bool   bAct = (tid < K_ * 8);                // 152 granules
    const float* bSrc0;
    uint32_t     bDst0;
    {
        const int g = bAct ? tid : 0;
        bSrc0 = g_probs + ((size_t)(b * K_) + (g >> 3)) * HW_ + s_off + (g & 7) * 4;
        bDst0 = SW128((uint32_t)g * 16u);
    }

    auto issue = [&](int t) {
        const uint32_t aS = aBase + (t % NBUF) * A_ST;
        const uint32_t bS = bBase + (t % NBUF) * B_ST;
        const int off = t * TS;
        #pragma unroll
        for (int j = 0; j < 4; j++)
            cpasync16(aS + aDst0 + j * 4096u, aSrc0 + (size_t)j * 32 * HW_ + off);
        if (bAct) cpasync16(bS + bDst0, bSrc0 + off);
    };

    // ---- fragment read addressing (analytic swizzle decomposition) ----
    const int rA = lane >> 2;                          // 0..7
    const int q  = lane & 3;
    const uint32_t mask = (uint32_t)rA * 16u;          // XOR mask, bits 4-6
    const uint32_t baseA0 = (uint32_t)(w * 16 + rA) * 128u + q * 4u;
    const uint32_t baseA1 = baseA0 + 8u * 128u;
    const uint32_t baseB0 = (uint32_t)rA * 128u + q * 4u;   // +nt*1024

    float d[3][4];
    #pragma unroll
    for (int nt = 0; nt < 3; nt++)
        #pragma unroll
        for (int j = 0; j < 4; j++) d[nt][j] = 0.0f;

    // prologue: 2 stages in flight
    issue(0); CP_COMMIT();
    issue(1); CP_COMMIT();

    for (int t = 0; t < NSl; ++t) {
        __syncthreads();                               // done reading recycled buffer
        if (t + 2 < NSl) { issue(t + 2); CP_COMMIT(); CP_WAIT(2); }
        else if (t + 1 < NSl) { CP_WAIT(1); }
        else                  { CP_WAIT(0); }
        __syncthreads();                               // stage t visible

        const uint32_t aS = aBase + (t % NBUF) * A_ST;
        const uint32_t bS = bBase + (t % NBUF) * B_ST;

        #pragma unroll
        for (int ch = 0; ch < 4; ++ch) {               // 8-s chunks
            const uint32_t c0 = (uint32_t)(ch * 32) ^ mask;        // s0..s0+3
            const uint32_t c1 = (uint32_t)(ch * 32 + 16) ^ mask;   // s0+4..s0+7
            const uint32_t ah0 = f2tf32(ldsf(aS + baseA0 + c0));
            const uint32_t ah1 = f2tf32(ldsf(aS + baseA1 + c0));
            const uint32_t ah2 = f2tf32(ldsf(aS + baseA0 + c1));
            const uint32_t ah3 = f2tf32(ldsf(aS + baseA1 + c1));
            #pragma unroll
            for (int nt = 0; nt < 3; ++nt) {
                const uint32_t b0 = ldsu(bS + baseB0 + nt * 1024u + c0);  // tf32 bits
                const uint32_t b1 = ldsu(bS + baseB0 + nt * 1024u + c1);
                MMA_TF32(d[nt], ah0, ah1, ah2, ah3, b0, b1);
            }
        }
    }

    // ---- epilogue: write split partials (each element exactly once) ----
    const int crow = ct * 128 + w * 16 + rA;
    const size_t o0 = ((size_t)(sp * B_ + b) * C_ + crow) * K_;
    const size_t o1 = ((size_t)(sp * B_ + b) * C_ + crow + 8) * K_;
    #pragma unroll
    for (int nt = 0; nt < 3; ++nt) {
        const int k0 = nt * 8 + 2 * q;
        if (k0 < K_) {
            g_part[o0 + k0] = d[nt][0];
            g_part[o1 + k0] = d[nt][2];
        }
        if (k0 + 1 < K_) {
            g_part[o0 + k0 + 1] = d[nt][1];
            g_part[o1 + k0 + 1] = d[nt][3];
        }
    }
}

// ---------------------------------------------------------------------------
// Kernel 3: out[i] = sum_split g_part[split][i]  (fixed order -> deterministic)
// ---------------------------------------------------------------------------
__global__ __launch_bounds__(256) void reduce_kernel(float* __restrict__ out) {
    const int i = blockIdx.x * 256 + threadIdx.x;
    if (i < B_ * C_ * K_) {
        float s = 0.0f;
        #pragma unroll
        for (int sp = 0; sp < NSPLIT; ++sp)
            s += g_part[(size_t)sp * (B_ * C_ * K_) + i];
        out[i] = s;
    }
}

extern "C" void kernel_launch(void* const* d_in, const int* in_sizes, int n_in,
                              void* d_out, int out_size) {
    const float* feats = (const float*)d_in[0];   // bb_feats [8,512,128,128]
    const float* aux   = (const float*)d_in[1];   // aux_out  [8,19,128,128]
    float* out = (float*)d_out;                   // [8,512,19,1] f32

    cudaFuncSetAttribute(gather_mma, cudaFuncAttributeMaxDynamicSharedMemorySize,
                         DYN_BYTES);

    softmax_kernel<<<B_ * K_, 256>>>(aux);
    gather_mma<<<B_ * 4 * NSPLIT, 256, DYN_BYTES>>>(feats);
    reduce_kernel<<<(B_ * C_ * K_ + 255) / 256, 256>>>(out);
}